// round 2
// baseline (speedup 1.0000x reference)
#include <cuda_runtime.h>
#include <cuda_bf16.h>

// Problem constants (HungarianMatcher: B=16, Q=900, C=92, T=1600)
#define BQ   14400      // B*Q
#define NC   92         // num classes
#define NT   1600       // num targets

#define COST_CLASS 1.0f
#define COST_BBOX  5.0f
#define COST_GIOU  2.0f

// Scratch: softmax probabilities [BQ, NC]  (5.3 MB, static device array — no allocs)
__device__ float g_prob[BQ * NC];

// ---------------------------------------------------------------------------
// Kernel 1: row-wise softmax of pred_logits [BQ, NC] -> g_prob
// One warp per row. NC=92 <= 96 = 3 lanes-worth of columns.
// ---------------------------------------------------------------------------
__global__ void softmax_rows_kernel(const float* __restrict__ logits) {
    int warps_per_block = blockDim.x >> 5;
    int row = blockIdx.x * warps_per_block + (threadIdx.x >> 5);
    if (row >= BQ) return;
    int lane = threadIdx.x & 31;

    const float* in = logits + (size_t)row * NC;
    float v0 = in[lane];                                   // lane      < 92 always
    float v1 = in[lane + 32];                              // lane+32   < 92 always
    float v2 = (lane + 64 < NC) ? in[lane + 64] : -1e30f;

    float m = fmaxf(v0, fmaxf(v1, v2));
    #pragma unroll
    for (int o = 16; o; o >>= 1) m = fmaxf(m, __shfl_xor_sync(0xffffffffu, m, o));

    float e0 = __expf(v0 - m);
    float e1 = __expf(v1 - m);
    float e2 = (lane + 64 < NC) ? __expf(v2 - m) : 0.0f;

    float s = e0 + e1 + e2;
    #pragma unroll
    for (int o = 16; o; o >>= 1) s += __shfl_xor_sync(0xffffffffu, s, o);

    float r = __fdividef(1.0f, s);
    float* outp = g_prob + (size_t)row * NC;
    outp[lane]      = e0 * r;
    outp[lane + 32] = e1 * r;
    if (lane + 64 < NC) outp[lane + 64] = e2 * r;
}

// ---------------------------------------------------------------------------
// Kernel 2: pair cost.  grid = (ceil(NT/256), BQ), block = 256 over t.
// Each block owns one query row q: pred box + softmax row cached in shared.
// Output out[q*NT + t] fp32, coalesced over t.
// ---------------------------------------------------------------------------
__global__ void cost_kernel(const float* __restrict__ pred_boxes,   // [BQ,4] cxcywh
                            const int*   __restrict__ tgt_labels,   // [NT] int32
                            const float* __restrict__ tgt_boxes,    // [NT,4] cxcywh
                            float*       __restrict__ out) {
    __shared__ float  s_prob[NC];
    __shared__ float4 s_pb;

    int q = blockIdx.y;
    if (threadIdx.x < NC)
        s_prob[threadIdx.x] = g_prob[(size_t)q * NC + threadIdx.x];
    if (threadIdx.x == 0)
        s_pb = reinterpret_cast<const float4*>(pred_boxes)[q];
    __syncthreads();

    int t = blockIdx.x * blockDim.x + threadIdx.x;
    if (t >= NT) return;

    float4 pb = s_pb;                                            // pred cxcywh
    float4 tb = reinterpret_cast<const float4*>(tgt_boxes)[t];   // tgt cxcywh
    int   lab = tgt_labels[t];
    lab = min(max(lab, 0), NC - 1);   // defensive clamp: never trap on a bad label

    // classification cost: -prob[q, label]
    float cclass = -s_prob[lab];

    // L1 box cost (cxcywh space)
    float cbbox = fabsf(pb.x - tb.x) + fabsf(pb.y - tb.y)
                + fabsf(pb.z - tb.z) + fabsf(pb.w - tb.w);

    // GIoU on xyxy boxes
    float p_x0 = pb.x - 0.5f * pb.z, p_y0 = pb.y - 0.5f * pb.w;
    float p_x1 = pb.x + 0.5f * pb.z, p_y1 = pb.y + 0.5f * pb.w;
    float t_x0 = tb.x - 0.5f * tb.z, t_y0 = tb.y - 0.5f * tb.w;
    float t_x1 = tb.x + 0.5f * tb.z, t_y1 = tb.y + 0.5f * tb.w;

    float area_p = (p_x1 - p_x0) * (p_y1 - p_y0);
    float area_t = (t_x1 - t_x0) * (t_y1 - t_y0);

    float iw = fmaxf(fminf(p_x1, t_x1) - fmaxf(p_x0, t_x0), 0.0f);
    float ih = fmaxf(fminf(p_y1, t_y1) - fmaxf(p_y0, t_y0), 0.0f);
    float inter = iw * ih;
    float uni   = area_p + area_t - inter;

    float ew = fmaxf(fmaxf(p_x1, t_x1) - fminf(p_x0, t_x0), 0.0f);
    float eh = fmaxf(fmaxf(p_y1, t_y1) - fminf(p_y0, t_y0), 0.0f);
    float enc = ew * eh;

    // giou = inter/uni - (enc-uni)/enc  ==  (inter*enc - (enc-uni)*uni) / (uni*enc)
    // -> single fast division per pair (MUFU pressure halved vs naive)
    float num  = fmaf(inter, enc, -(enc - uni) * uni);
    float den  = uni * enc;
    float giou = __fdividef(num, den);

    out[(size_t)q * NT + t] = COST_BBOX * cbbox + COST_CLASS * cclass - COST_GIOU * giou;
}

// ---------------------------------------------------------------------------
extern "C" void kernel_launch(void* const* d_in, const int* in_sizes, int n_in,
                              void* d_out, int out_size) {
    const float* pred_logits = (const float*)d_in[0];  // [16,900,92]
    const float* pred_boxes  = (const float*)d_in[1];  // [16,900,4]
    const int*   tgt_labels  = (const int*)  d_in[2];  // [1600] int32 (JAX x64 off)
    const float* tgt_boxes   = (const float*)d_in[3];  // [1600,4]
    float*       out         = (float*)d_out;          // [16,900,1600]

    (void)in_sizes; (void)n_in; (void)out_size;

    // Kernel 1: softmax rows. 8 warps/block -> 1800 blocks.
    {
        int warps_per_block = 8;
        int threads = warps_per_block * 32;
        int blocks  = (BQ + warps_per_block - 1) / warps_per_block;
        softmax_rows_kernel<<<blocks, threads>>>(pred_logits);
    }

    // Kernel 2: pair costs. grid (7, 14400), 256 threads.
    {
        dim3 block(256, 1, 1);
        dim3 grid((NT + block.x - 1) / block.x, BQ, 1);
        cost_kernel<<<grid, block>>>(pred_boxes, tgt_labels, tgt_boxes, out);
    }
}

// round 3
// speedup vs baseline: 2.1603x; 2.1603x over previous
#include <cuda_runtime.h>
#include <cuda_bf16.h>

// Problem constants (HungarianMatcher: B=16, Q=900, C=92, T=1600)
#define BQ   14400      // B*Q
#define NC   92         // num classes
#define NT   1600       // num targets

#define QT   36         // queries per block (900 = 25*36)
#define TT   320        // threads per block = targets per block (1600 = 5*320)

// Scratch: softmax probabilities [BQ, NC]  (5.3 MB, static device array — no allocs)
__device__ float g_prob[BQ * NC];

// ---------------------------------------------------------------------------
// Kernel 1: row-wise softmax of pred_logits [BQ, NC] -> g_prob
// One warp per row. NC=92 <= 96 = 3 lanes-worth of columns.
// ---------------------------------------------------------------------------
__global__ void softmax_rows_kernel(const float* __restrict__ logits) {
    int warps_per_block = blockDim.x >> 5;
    int row = blockIdx.x * warps_per_block + (threadIdx.x >> 5);
    if (row >= BQ) return;
    int lane = threadIdx.x & 31;

    const float* in = logits + (size_t)row * NC;
    float v0 = in[lane];
    float v1 = in[lane + 32];
    float v2 = (lane + 64 < NC) ? in[lane + 64] : -1e30f;

    float m = fmaxf(v0, fmaxf(v1, v2));
    #pragma unroll
    for (int o = 16; o; o >>= 1) m = fmaxf(m, __shfl_xor_sync(0xffffffffu, m, o));

    float e0 = __expf(v0 - m);
    float e1 = __expf(v1 - m);
    float e2 = (lane + 64 < NC) ? __expf(v2 - m) : 0.0f;

    float s = e0 + e1 + e2;
    #pragma unroll
    for (int o = 16; o; o >>= 1) s += __shfl_xor_sync(0xffffffffu, s, o);

    float r = __fdividef(1.0f, s);
    float* outp = g_prob + (size_t)row * NC;
    outp[lane]      = e0 * r;
    outp[lane + 32] = e1 * r;
    if (lane + 64 < NC) outp[lane + 64] = e2 * r;
}

// ---------------------------------------------------------------------------
// Kernel 2: pair cost with q-tiling.
// grid = (NT/TT = 5, BQ/QT = 400), block = TT = 320 threads.
// Thread owns one target t (box + label + xyxy precomputed in registers),
// loops over QT queries whose data is warp-uniform in shared memory.
// Output out[q*NT + t] fp32, coalesced over t.
// ---------------------------------------------------------------------------
__global__ __launch_bounds__(TT) void cost_kernel(
        const float* __restrict__ pred_boxes,   // [BQ,4] cxcywh
        const int*   __restrict__ tgt_labels,   // [NT] int32
        const float* __restrict__ tgt_boxes,    // [NT,4] cxcywh
        float*       __restrict__ out) {
    __shared__ float4 s_cw[QT];            // pred cxcywh
    __shared__ float4 s_xy[QT];            // pred xyxy
    __shared__ float  s_ar[QT];            // pred area
    __shared__ float  s_prob[QT * NC];     // softmax rows for this q-tile

    const int tid = threadIdx.x;
    const int q0  = blockIdx.y * QT;

    // Coalesced fill of the probability tile (36*92 = 3312 floats).
    const float* gp = g_prob + (size_t)q0 * NC;
    #pragma unroll
    for (int i = tid; i < QT * NC; i += TT) s_prob[i] = gp[i];

    // Per-q box precompute (36 threads).
    if (tid < QT) {
        float4 b = reinterpret_cast<const float4*>(pred_boxes)[q0 + tid];
        s_cw[tid] = b;
        float4 xy = make_float4(b.x - 0.5f * b.z, b.y - 0.5f * b.w,
                                b.x + 0.5f * b.z, b.y + 0.5f * b.w);
        s_xy[tid] = xy;
        s_ar[tid] = (xy.z - xy.x) * (xy.w - xy.y);
    }
    __syncthreads();

    // Target-side: loaded ONCE per thread.
    const int t = blockIdx.x * TT + tid;                        // < 1600 always
    float4 tb = reinterpret_cast<const float4*>(tgt_boxes)[t];
    int lab = tgt_labels[t];
    lab = min(max(lab, 0), NC - 1);

    const float tx0 = tb.x - 0.5f * tb.z, ty0 = tb.y - 0.5f * tb.w;
    const float tx1 = tb.x + 0.5f * tb.z, ty1 = tb.y + 0.5f * tb.w;
    const float area_t = (tx1 - tx0) * (ty1 - ty0);

    float* outp = out + (size_t)q0 * NT + t;

    #pragma unroll 4
    for (int j = 0; j < QT; j++) {
        float4 pc  = s_cw[j];      // warp-uniform LDS.128 broadcast
        float4 pxy = s_xy[j];
        float  area_p = s_ar[j];

        // L1 box cost (cxcywh)
        float cb = fabsf(pc.x - tb.x) + fabsf(pc.y - tb.y)
                 + fabsf(pc.z - tb.z) + fabsf(pc.w - tb.w);

        // GIoU
        float iw = fmaxf(fminf(pxy.z, tx1) - fmaxf(pxy.x, tx0), 0.0f);
        float ih = fmaxf(fminf(pxy.w, ty1) - fmaxf(pxy.y, ty0), 0.0f);
        float inter = iw * ih;
        float uni   = area_p + area_t - inter;

        float ew = fmaxf(pxy.z, tx1) - fminf(pxy.x, tx0);
        float eh = fmaxf(pxy.w, ty1) - fminf(pxy.y, ty0);
        float enc = ew * eh;

        // giou = (inter*enc - (enc-uni)*uni) / (uni*enc): one RCP per pair
        float num  = fmaf(inter, enc, -(enc - uni) * uni);
        float giou = __fdividef(num, uni * enc);

        // cost = 5*cb - prob - 2*giou
        float c = fmaf(5.0f, cb, fmaf(-2.0f, giou, -s_prob[j * NC + lab]));

        outp[(size_t)j * NT] = c;
    }
}

// ---------------------------------------------------------------------------
extern "C" void kernel_launch(void* const* d_in, const int* in_sizes, int n_in,
                              void* d_out, int out_size) {
    const float* pred_logits = (const float*)d_in[0];  // [16,900,92]
    const float* pred_boxes  = (const float*)d_in[1];  // [16,900,4]
    const int*   tgt_labels  = (const int*)  d_in[2];  // [1600] int32
    const float* tgt_boxes   = (const float*)d_in[3];  // [1600,4]
    float*       out         = (float*)d_out;          // [16,900,1600]

    (void)in_sizes; (void)n_in; (void)out_size;

    // Kernel 1: softmax rows. 8 warps/block -> 1800 blocks.
    {
        int warps_per_block = 8;
        int threads = warps_per_block * 32;
        int blocks  = (BQ + warps_per_block - 1) / warps_per_block;
        softmax_rows_kernel<<<blocks, threads>>>(pred_logits);
    }

    // Kernel 2: pair costs. grid (5, 400), 320 threads — exact tiling, no tails.
    {
        dim3 block(TT, 1, 1);
        dim3 grid(NT / TT, BQ / QT, 1);
        cost_kernel<<<grid, block>>>(pred_boxes, tgt_labels, tgt_boxes, out);
    }
}

// round 4
// speedup vs baseline: 2.2865x; 1.0584x over previous
#include <cuda_runtime.h>
#include <cuda_bf16.h>

// Problem constants (HungarianMatcher: B=16, Q=900, C=92, T=1600)
#define BQ   14400      // B*Q
#define NC   92         // num classes
#define NT   1600       // num targets

#define QT   36         // queries per block (14400 = 400*36)
#define THREADS 160     // threads per block; each owns 2 targets -> 320 t/block

// Scratch: softmax probabilities [BQ, NC]  (5.3 MB, static device array — no allocs)
__device__ float g_prob[BQ * NC];

// ---------------------------------------------------------------------------
// Kernel 1: row-wise softmax of pred_logits [BQ, NC] -> g_prob. Warp per row.
// ---------------------------------------------------------------------------
__global__ void softmax_rows_kernel(const float* __restrict__ logits) {
    int warps_per_block = blockDim.x >> 5;
    int row = blockIdx.x * warps_per_block + (threadIdx.x >> 5);
    if (row >= BQ) return;
    int lane = threadIdx.x & 31;

    const float* in = logits + (size_t)row * NC;
    float v0 = in[lane];
    float v1 = in[lane + 32];
    float v2 = (lane + 64 < NC) ? in[lane + 64] : -1e30f;

    float m = fmaxf(v0, fmaxf(v1, v2));
    #pragma unroll
    for (int o = 16; o; o >>= 1) m = fmaxf(m, __shfl_xor_sync(0xffffffffu, m, o));

    float e0 = __expf(v0 - m);
    float e1 = __expf(v1 - m);
    float e2 = (lane + 64 < NC) ? __expf(v2 - m) : 0.0f;

    float s = e0 + e1 + e2;
    #pragma unroll
    for (int o = 16; o; o >>= 1) s += __shfl_xor_sync(0xffffffffu, s, o);

    float r = __fdividef(1.0f, s);
    float* outp = g_prob + (size_t)row * NC;
    outp[lane]      = e0 * r;
    outp[lane + 32] = e1 * r;
    if (lane + 64 < NC) outp[lane + 64] = e2 * r;
}

// ---------------------------------------------------------------------------
// Per-pair cost. ~31 SASS ops. Uses enclosing-box identity:
//   ew = (wp + wt) - iwu   (since max(a,b)+min(a,b) = a+b)
// nprob = -prob[q][lab] precomputed by caller.
// ---------------------------------------------------------------------------
__device__ __forceinline__ float pair_cost(
        float4 pc, float4 pxy, float area_p,
        float tx0, float ty0, float tx1, float ty1,
        float tcx, float tcy, float tw, float th,
        float area_t, float nprob) {
    float ax  = fmaxf(pxy.x, tx0);
    float bx  = fminf(pxy.z, tx1);
    float iwu = bx - ax;                       // unclamped intersection w
    float ay  = fmaxf(pxy.y, ty0);
    float by  = fminf(pxy.w, ty1);
    float ihu = by - ay;

    float iw = fmaxf(iwu, 0.0f);
    float ih = fmaxf(ihu, 0.0f);
    float inter = iw * ih;

    float ew  = (pc.z + tw) - iwu;             // enclosing w via identity
    float eh  = (pc.w + th) - ihu;
    float enc = ew * eh;

    float sumA = area_p + area_t;
    float uni  = sumA - inter;
    float emu  = enc - uni;
    float num  = fmaf(inter, enc, -emu * uni); // inter*enc - (enc-uni)*uni
    float giou = __fdividef(num, uni * enc);

    float cb = fabsf(pc.x - tcx) + fabsf(pc.y - tcy)
             + fabsf(pc.z - tw)  + fabsf(pc.w - th);

    return fmaf(5.0f, cb, fmaf(-2.0f, giou, nprob));
}

// ---------------------------------------------------------------------------
// Kernel 2: pair cost, q-tiled, dual-target threads.
// grid = (NT/(2*THREADS) = 5, BQ/QT = 400), block = 160.
// Thread owns targets t0 = base+2*tid, t0+1; loops QT queries from shared.
// Stores float2 (coalesced STG.64 over t).
// ---------------------------------------------------------------------------
__global__ __launch_bounds__(THREADS) void cost_kernel(
        const float* __restrict__ pred_boxes,   // [BQ,4] cxcywh
        const int*   __restrict__ tgt_labels,   // [NT] int32
        const float* __restrict__ tgt_boxes,    // [NT,4] cxcywh
        float*       __restrict__ out) {
    __shared__ float4 s_xy[QT];            // pred xyxy
    __shared__ float4 s_cw[QT];            // pred cxcywh
    __shared__ float  s_prob[QT * NC];     // softmax rows for this q-tile

    const int tid = threadIdx.x;
    const int q0  = blockIdx.y * QT;

    // Coalesced fill of the probability tile (36*92 = 3312 floats).
    const float* gp = g_prob + (size_t)q0 * NC;
    #pragma unroll
    for (int i = tid; i < QT * NC; i += THREADS) s_prob[i] = gp[i];

    if (tid < QT) {
        float4 b = reinterpret_cast<const float4*>(pred_boxes)[q0 + tid];
        s_cw[tid] = b;
        s_xy[tid] = make_float4(b.x - 0.5f * b.z, b.y - 0.5f * b.w,
                                b.x + 0.5f * b.z, b.y + 0.5f * b.w);
    }
    __syncthreads();

    // Two targets per thread, loaded once.
    const int t0 = blockIdx.x * (2 * THREADS) + 2 * tid;
    float4 ta = reinterpret_cast<const float4*>(tgt_boxes)[t0];
    float4 tb = reinterpret_cast<const float4*>(tgt_boxes)[t0 + 1];
    int la = min(max(tgt_labels[t0],     0), NC - 1);
    int lb = min(max(tgt_labels[t0 + 1], 0), NC - 1);

    const float ax0 = ta.x - 0.5f * ta.z, ay0 = ta.y - 0.5f * ta.w;
    const float ax1 = ta.x + 0.5f * ta.z, ay1 = ta.y + 0.5f * ta.w;
    const float areaA = ta.z * ta.w;

    const float bx0 = tb.x - 0.5f * tb.z, by0 = tb.y - 0.5f * tb.w;
    const float bx1 = tb.x + 0.5f * tb.z, by1 = tb.y + 0.5f * tb.w;
    const float areaB = tb.z * tb.w;

    float2* outp = reinterpret_cast<float2*>(out + (size_t)q0 * NT + t0);

    #pragma unroll 6
    for (int j = 0; j < QT; j++) {
        float4 pxy = s_xy[j];              // warp-uniform LDS.128 broadcast
        float4 pc  = s_cw[j];
        float  area_p = pc.z * pc.w;       // 1 FMUL shared by 2 pairs
        const float* pr = s_prob + j * NC;

        float c0 = pair_cost(pc, pxy, area_p, ax0, ay0, ax1, ay1,
                             ta.x, ta.y, ta.z, ta.w, areaA, -pr[la]);
        float c1 = pair_cost(pc, pxy, area_p, bx0, by0, bx1, by1,
                             tb.x, tb.y, tb.z, tb.w, areaB, -pr[lb]);

        outp[(size_t)j * (NT / 2)] = make_float2(c0, c1);
    }
}

// ---------------------------------------------------------------------------
extern "C" void kernel_launch(void* const* d_in, const int* in_sizes, int n_in,
                              void* d_out, int out_size) {
    const float* pred_logits = (const float*)d_in[0];  // [16,900,92]
    const float* pred_boxes  = (const float*)d_in[1];  // [16,900,4]
    const int*   tgt_labels  = (const int*)  d_in[2];  // [1600] int32
    const float* tgt_boxes   = (const float*)d_in[3];  // [1600,4]
    float*       out         = (float*)d_out;          // [16,900,1600]

    (void)in_sizes; (void)n_in; (void)out_size;

    // Kernel 1: softmax rows. 8 warps/block -> 1800 blocks.
    {
        int warps_per_block = 8;
        int threads = warps_per_block * 32;
        int blocks  = (BQ + warps_per_block - 1) / warps_per_block;
        softmax_rows_kernel<<<blocks, threads>>>(pred_logits);
    }

    // Kernel 2: pair costs. grid (5, 400), 160 threads, 2 targets/thread.
    {
        dim3 block(THREADS, 1, 1);
        dim3 grid(NT / (2 * THREADS), BQ / QT, 1);
        cost_kernel<<<grid, block>>>(pred_boxes, tgt_labels, tgt_boxes, out);
    }
}